// round 16
// baseline (speedup 1.0000x reference)
#include <cuda_runtime.h>
#include <cuda_bf16.h>
#include <cstdint>
#include <cstddef>

#define BB    64
#define TT    20
#define EMBD  512
#define VOC   32000
#define NSTEP 19
#define GDIM  2048
#define ETILE 4
#define NCTA  128
#define MPAD  1280          // padded xpre/emb row count (10 * 128)
#define KEXT  1536          // extended K for 3xTF32-as-one-pass (xpre)
#define KW    256           // words per 512 bf16 pairs
#define KEXTW 768           // words per ext row (3 * 256)

// ---------------- scratch (no allocations allowed) ----------------
__device__ float    g_emb_ext[MPAD * KEXT];     // [Ah | Al | Ah] per row (tf32)
__device__ float    g_wih_ext[GDIM * KEXT];     // [Wh | Wh | Wl] per row (tf32)
__device__ float    g_seq[BB * TT * EMBD];      // tf32-ROUNDED values (proj input)
__device__ float    g_xpre[MPAD * GDIM];        // [t*64+b][4E]
__device__ float    g_c[BB * EMBD];
__device__ unsigned g_hx2[BB * KEXTW];          // h as bf16 pairs: [Hh | Hl | Hh]
__device__ unsigned g_whhx2[GDIM * KEXTW];      // W_hh bf16 pairs: [Wh | Wh | Wl]
__device__ float    g_wout_r[VOC * EMBD];       // W_out tf32-rounded

// ---------------- helpers ----------------
__device__ __forceinline__ unsigned f2tf(float x) {
    unsigned u;
    asm("cvt.rna.tf32.f32 %0, %1;" : "=r"(u) : "f"(x));
    return u;
}
__device__ __forceinline__ float tfr(float x) { return __uint_as_float(f2tf(x)); }

__device__ __forceinline__ void mma8(float c[4], const unsigned a[4], const unsigned b[2]) {
    asm volatile(
        "mma.sync.aligned.m16n8k8.row.col.f32.tf32.tf32.f32 "
        "{%0,%1,%2,%3}, {%4,%5,%6,%7}, {%8,%9}, {%0,%1,%2,%3};"
        : "+f"(c[0]), "+f"(c[1]), "+f"(c[2]), "+f"(c[3])
        : "r"(a[0]), "r"(a[1]), "r"(a[2]), "r"(a[3]), "r"(b[0]), "r"(b[1]));
}

__device__ __forceinline__ void mma16bf(float c[4], const unsigned a[4], const unsigned b[2]) {
    asm volatile(
        "mma.sync.aligned.m16n8k16.row.col.f32.bf16.bf16.f32 "
        "{%0,%1,%2,%3}, {%4,%5,%6,%7}, {%8,%9}, {%0,%1,%2,%3};"
        : "+f"(c[0]), "+f"(c[1]), "+f"(c[2]), "+f"(c[3])
        : "r"(a[0]), "r"(a[1]), "r"(a[2]), "r"(a[3]), "r"(b[0]), "r"(b[1]));
}

__device__ __forceinline__ float fsig(float x) { return 1.f / (1.f + __expf(-x)); }
__device__ __forceinline__ float ftanh(float x) {
    float e = __expf(-2.f * x);
    return (1.f - e) / (1.f + e);
}

// pack two floats to a bf16x2 word: low half = a (lower k index), high = b
__device__ __forceinline__ unsigned pack_bf2(float a, float b) {
    __nv_bfloat162 v = __floats2bfloat162_rn(a, b);   // .x -> low half
    return *(unsigned*)&v;
}
__device__ __forceinline__ float bf_lo_res(float x) {  // x - bf16(x)
    return x - __bfloat162float(__float2bfloat16_rn(x));
}

// ---------------- init: emb ext gather + h0/c0/seq0 ----------------
__global__ void init_kernel(const float* __restrict__ features,
                            const int*   __restrict__ captions,
                            const float* __restrict__ W_emb) {
    int idx = blockIdx.x * blockDim.x + threadIdx.x;       // over B*T*(E/4)
    if (idx >= BB * TT * (EMBD / 4)) return;
    int e4 = idx & (EMBD / 4 - 1);
    int bt = idx >> 7;
    int t = bt % TT, b = bt / TT;
    int cap = captions[b * TT + t];
    float4 v = *(const float4*)(W_emb + (size_t)cap * EMBD + e4 * 4);
    float4 hi = make_float4(tfr(v.x), tfr(v.y), tfr(v.z), tfr(v.w));
    float4 lo = make_float4(tfr(v.x - hi.x), tfr(v.y - hi.y),
                            tfr(v.z - hi.z), tfr(v.w - hi.w));
    if (t < NSTEP) {
        float* row = g_emb_ext + (size_t)(t * BB + b) * KEXT;
        *(float4*)(row + e4 * 4)        = hi;   // Ah
        *(float4*)(row + 512 + e4 * 4)  = lo;   // Al
        *(float4*)(row + 1024 + e4 * 4) = hi;   // Ah (for Ah*Bl term)
    }
    if (t == 0) {
        *(float4*)(g_seq + ((size_t)b * TT) * EMBD + e4 * 4) = hi;        // seq[:,0]
        // zero h (bf16-pair ext): words 2*e4, 2*e4+1 in each of 3 segments
        unsigned* hrow = g_hx2 + (size_t)b * KEXTW;
        hrow[e4 * 2] = 0u;       hrow[e4 * 2 + 1] = 0u;
        hrow[256 + e4 * 2] = 0u; hrow[256 + e4 * 2 + 1] = 0u;
        hrow[512 + e4 * 2] = 0u; hrow[512 + e4 * 2 + 1] = 0u;
        *(float4*)(g_c + (size_t)b * EMBD + e4 * 4) =
            *(const float4*)(features + (size_t)b * EMBD + e4 * 4);       // c0
    }
}

// ---------------- preps ----------------
__global__ void prep_wih(const float* __restrict__ W) {
    int i = blockIdx.x * blockDim.x + threadIdx.x;   // over GDIM*EMBD/4
    if (i >= GDIM * EMBD / 4) return;
    int row = i >> 7, c4 = i & 127;
    float4 w = ((const float4*)W)[i];
    float4 hi = make_float4(tfr(w.x), tfr(w.y), tfr(w.z), tfr(w.w));
    float4 lo = make_float4(tfr(w.x - hi.x), tfr(w.y - hi.y),
                            tfr(w.z - hi.z), tfr(w.w - hi.w));
    float* dst = g_wih_ext + (size_t)row * KEXT;
    *(float4*)(dst + c4 * 4)        = hi;   // Bh
    *(float4*)(dst + 512 + c4 * 4)  = hi;   // Bh (pairs with Al)
    *(float4*)(dst + 1024 + c4 * 4) = lo;   // Bl (pairs with Ah)
}

// W_hh -> bf16-pair ext rows [Wh | Wh | Wl]
__global__ void prep_whhx2(const float* __restrict__ W) {
    int i = blockIdx.x * blockDim.x + threadIdx.x;   // over GDIM*KW
    if (i >= GDIM * KW) return;
    int row = i >> 8, wq = i & 255;
    float w0 = W[(size_t)row * EMBD + wq * 2];
    float w1 = W[(size_t)row * EMBD + wq * 2 + 1];
    unsigned hh = pack_bf2(w0, w1);
    unsigned ll = pack_bf2(bf_lo_res(w0), bf_lo_res(w1));
    unsigned* dst = g_whhx2 + (size_t)row * KEXTW;
    dst[wq]       = hh;
    dst[256 + wq] = hh;
    dst[512 + wq] = ll;
}

__global__ void prep_wout(const float* __restrict__ W) {
    int i = blockIdx.x * blockDim.x + threadIdx.x;   // over VOC*EMBD/4
    if (i >= VOC * EMBD / 4) return;
    float4 w = ((const float4*)W)[i];
    ((float4*)g_wout_r)[i] = make_float4(tfr(w.x), tfr(w.y), tfr(w.z), tfr(w.w));
}

// ---------------- pre-rounded TF32 GEMM: C = A * B^T (+bias) ----
// MX: if true, M tile on blockIdx.x (so CTAs sharing a B tile are co-resident).
template <int BM, int BN, int WM, int WN, int THREADS, bool MX>
__global__ void __launch_bounds__(THREADS)
gemm_pre(const float* __restrict__ A, const float* __restrict__ B,
         float* __restrict__ C,
         const float* __restrict__ bias0, const float* __restrict__ bias1,
         int M, int N, int K, int lda, int ldb) {
    constexpr int BK = 8, LD = 12;
    constexpr int WROWS = BM / WM, WCOLS = BN / WN;
    constexpr int MT = WROWS / 16, NT = WCOLS / 8;
    static_assert(WM * WN == THREADS / 32, "warp grid");

    __shared__ __align__(16) float As[2 * BM * LD];
    __shared__ __align__(16) float Bs[2 * BN * LD];

    const int tid = threadIdx.x, lane = tid & 31, w = tid >> 5;
    const int wm = w / WN, wn = w % WN;
    const int r = lane >> 2, cq = lane & 3;
    const int rowA0 = (MX ? blockIdx.x : blockIdx.y) * BM;
    const int rowB0 = (MX ? blockIdx.y : blockIdx.x) * BN;

    const uint32_t sA = (uint32_t)__cvta_generic_to_shared(As);
    const uint32_t sB = (uint32_t)__cvta_generic_to_shared(Bs);

    float acc[MT][NT][4] = {};

    auto stage = [&](int kt, int s) {
        for (int i = tid; i < BM * 2; i += THREADS) {
            int row = i >> 1, kq = i & 1;
            const float* src = A + (size_t)(rowA0 + row) * lda + kt * BK + kq * 4;
            uint32_t dst = sA + (uint32_t)((s * BM + row) * LD + kq * 4) * 4;
            asm volatile("cp.async.cg.shared.global [%0], [%1], 16;\n"
                         :: "r"(dst), "l"(src));
        }
        for (int i = tid; i < BN * 2; i += THREADS) {
            int row = i >> 1, kq = i & 1;
            const float* src = B + (size_t)(rowB0 + row) * ldb + kt * BK + kq * 4;
            uint32_t dst = sB + (uint32_t)((s * BN + row) * LD + kq * 4) * 4;
            asm volatile("cp.async.cg.shared.global [%0], [%1], 16;\n"
                         :: "r"(dst), "l"(src));
        }
        asm volatile("cp.async.commit_group;\n");
    };

    const int KT = K / BK;
    stage(0, 0);
    for (int kt = 0; kt < KT; kt++) {
        const int s = kt & 1;
        if (kt + 1 < KT) {
            stage(kt + 1, s ^ 1);
            asm volatile("cp.async.wait_group 1;\n");
        } else {
            asm volatile("cp.async.wait_group 0;\n");
        }
        __syncthreads();

        const float* At = As + s * BM * LD;
        const float* Bt = Bs + s * BN * LD;

        unsigned ah[MT][4];
#pragma unroll
        for (int mi = 0; mi < MT; mi++) {
            int m0 = wm * WROWS + mi * 16;
            ah[mi][0] = __float_as_uint(At[(m0 + r) * LD + cq]);
            ah[mi][1] = __float_as_uint(At[(m0 + r + 8) * LD + cq]);
            ah[mi][2] = __float_as_uint(At[(m0 + r) * LD + cq + 4]);
            ah[mi][3] = __float_as_uint(At[(m0 + r + 8) * LD + cq + 4]);
        }
#pragma unroll
        for (int ni = 0; ni < NT; ni++) {
            int n0 = wn * WCOLS + ni * 8;
            unsigned bh[2] = {__float_as_uint(Bt[(n0 + r) * LD + cq]),
                              __float_as_uint(Bt[(n0 + r) * LD + cq + 4])};
#pragma unroll
            for (int mi = 0; mi < MT; mi++)
                mma8(acc[mi][ni], ah[mi], bh);
        }
        __syncthreads();
    }

#pragma unroll
    for (int mi = 0; mi < MT; mi++) {
        const int row0 = rowA0 + wm * WROWS + mi * 16 + r;
#pragma unroll
        for (int ni = 0; ni < NT; ni++) {
            const int col = rowB0 + wn * WCOLS + ni * 8 + 2 * cq;
            float b0 = 0.f, b1 = 0.f;
            if (bias0) { b0 += bias0[col]; b1 += bias0[col + 1]; }
            if (bias1) { b0 += bias1[col]; b1 += bias1[col + 1]; }
            float2 o0, o1;
            o0.x = acc[mi][ni][0] + b0;
            o0.y = acc[mi][ni][1] + b1;
            o1.x = acc[mi][ni][2] + b0;
            o1.y = acc[mi][ni][3] + b1;
            *(float2*)(C + (size_t)row0 * N + col) = o0;
            *(float2*)(C + (size_t)(row0 + 8) * N + col) = o1;
        }
    }
}

// ---------------- fused LSTM step, split-bf16 (zero alu in mainloop) ---------
// Same structure as R7 (measured-correct): CTA c owns e in [4c,4c+4); 8 warps =
// 4 K-groups x 2 n-halves; per-kg K = KEXTW/4 = 192 words = 24 BK8-word ktiles.
// Operands: g_hx2 [Hh|Hl|Hh] vs g_whhx2 [Wh|Wh|Wl] -> HhWh + HlWh + HhWl.
__global__ void __launch_bounds__(256)
step_kernel(int s) {
    constexpr int LD = 12;                        // words per smem row (conflict-free)
    __shared__ unsigned As[2][4][64][LD];         // 24576 B
    __shared__ unsigned Bs[2][4][16][LD];         //  6144 B
    __shared__ float    P[4][64][16];             // 16384 B
    __shared__ float    Hs[64][4];                //  1024 B

    const int c = blockIdx.x;
    const int tid = threadIdx.x, lane = tid & 31, w = tid >> 5;
    const int kg = w >> 1, nh = w & 1;
    const int r = lane >> 2, cq = lane & 3;

    const uint32_t sA = (uint32_t)__cvta_generic_to_shared(&As[0][0][0][0]);
    const uint32_t sB = (uint32_t)__cvta_generic_to_shared(&Bs[0][0][0][0]);

    auto stage = [&](int kt, int st) {
        // A: 4 kg * 64 rows * 2 halves of 4 words (16B)
        for (int i = tid; i < 512; i += 256) {
            int g = i >> 7, rem = i & 127, row = rem >> 1, half = rem & 1;
            const unsigned* src = g_hx2 + (size_t)row * KEXTW + g * 192 + kt * 8 + half * 4;
            uint32_t dst = sA + (uint32_t)(((st * 4 + g) * 64 + row) * LD + half * 4) * 4;
            asm volatile("cp.async.cg.shared.global [%0], [%1], 16;\n"
                         :: "r"(dst), "l"(src));
        }
        // B: 4 kg * 16 gate-rows * 2 halves
        for (int i = tid; i < 128; i += 256) {
            int g = i >> 5, rem = i & 31, row = rem >> 1, half = rem & 1;
            int grow = (row >> 2) * 512 + c * ETILE + (row & 3);
            const unsigned* src = g_whhx2 + (size_t)grow * KEXTW + g * 192 + kt * 8 + half * 4;
            uint32_t dst = sB + (uint32_t)(((st * 4 + g) * 16 + row) * LD + half * 4) * 4;
            asm volatile("cp.async.cg.shared.global [%0], [%1], 16;\n"
                         :: "r"(dst), "l"(src));
        }
        asm volatile("cp.async.commit_group;\n");
    };

    float acc[4][4] = {};

    stage(0, 0);
    for (int kt = 0; kt < 24; kt++) {             // 192 words / 8 per ktile
        const int st = kt & 1;
        if (kt + 1 < 24) {
            stage(kt + 1, st ^ 1);
            asm volatile("cp.async.wait_group 1;\n");
        } else {
            asm volatile("cp.async.wait_group 0;\n");
        }
        __syncthreads();

        const unsigned (*At)[LD] = As[st][kg];
        const unsigned (*Bt)[LD] = Bs[st][kg];

        unsigned bh[2] = {Bt[nh * 8 + r][cq], Bt[nh * 8 + r][cq + 4]};
#pragma unroll
        for (int mi = 0; mi < 4; mi++) {
            int m0 = mi * 16;
            unsigned ah[4] = {At[m0 + r][cq], At[m0 + r + 8][cq],
                              At[m0 + r][cq + 4], At[m0 + r + 8][cq + 4]};
            mma16bf(acc[mi], ah, bh);
        }
        __syncthreads();
    }

    // per-K-group partials
#pragma unroll
    for (int mi = 0; mi < 4; mi++) {
        int row = mi * 16 + r;
        int col = nh * 8 + 2 * cq;
        P[kg][row][col]     = acc[mi][0];
        P[kg][row][col + 1] = acc[mi][1];
        P[kg][row + 8][col]     = acc[mi][2];
        P[kg][row + 8][col + 1] = acc[mi][3];
    }
    __syncthreads();

    // cell
    {
        int b = tid >> 2, j = tid & 3;
        int e = c * ETILE + j;
        const float* xp = g_xpre + ((size_t)s * BB + b) * GDIM;
        float gi = xp[e]        + P[0][b][j]      + P[1][b][j]      + P[2][b][j]      + P[3][b][j];
        float gf = xp[512 + e]  + P[0][b][4 + j]  + P[1][b][4 + j]  + P[2][b][4 + j]  + P[3][b][4 + j];
        float gg = xp[1024 + e] + P[0][b][8 + j]  + P[1][b][8 + j]  + P[2][b][8 + j]  + P[3][b][8 + j];
        float go = xp[1536 + e] + P[0][b][12 + j] + P[1][b][12 + j] + P[2][b][12 + j] + P[3][b][12 + j];
        float cold = g_c[b * EMBD + e];
        float cn = fsig(gf) * cold + fsig(gi) * ftanh(gg);
        float hn = fsig(go) * ftanh(cn);
        g_c[b * EMBD + e] = cn;
        Hs[b][j] = hn;
        g_seq[((size_t)b * TT + (s + 1)) * EMBD + e] = tfr(hn);   // pre-rounded for proj
    }
    __syncthreads();

    // pack h into bf16-pair ext rows (threads j<2 handle one word each)
    {
        int b = tid >> 2, j = tid & 3;
        if (j < 2) {
            float h0 = Hs[b][2 * j], h1 = Hs[b][2 * j + 1];
            unsigned hh = pack_bf2(h0, h1);
            unsigned ll = pack_bf2(bf_lo_res(h0), bf_lo_res(h1));
            unsigned* dst = g_hx2 + (size_t)b * KEXTW + 2 * c + j;
            dst[0]   = hh;   // seg0: Hh
            dst[256] = ll;   // seg1: Hl
            dst[512] = hh;   // seg2: Hh
        }
    }
}

// ---------------- launch ----------------
extern "C" void kernel_launch(void* const* d_in, const int* in_sizes, int n_in,
                              void* d_out, int out_size) {
    const float* features = (const float*)d_in[0];
    const int*   captions = (const int*)d_in[1];
    const float* W_emb    = (const float*)d_in[2];
    const float* W_out    = (const float*)d_in[3];
    const float* b_out    = (const float*)d_in[4];
    const float* W_ih     = (const float*)d_in[5];
    const float* W_hh     = (const float*)d_in[6];
    const float* b_ih     = (const float*)d_in[7];
    const float* b_hh     = (const float*)d_in[8];
    float* out = (float*)d_out;
    (void)in_sizes; (void)n_in; (void)out_size;

    float *p_embext, *p_wihext, *p_xpre, *p_seq, *p_wout;
    cudaGetSymbolAddress((void**)&p_embext, g_emb_ext);
    cudaGetSymbolAddress((void**)&p_wihext, g_wih_ext);
    cudaGetSymbolAddress((void**)&p_xpre,   g_xpre);
    cudaGetSymbolAddress((void**)&p_seq,    g_seq);
    cudaGetSymbolAddress((void**)&p_wout,   g_wout_r);

    // 1) init + weight preps
    init_kernel<<<(BB * TT * (EMBD / 4) + 255) / 256, 256>>>(features, captions, W_emb);
    prep_wih<<<(GDIM * EMBD / 4 + 255) / 256, 256>>>(W_ih);
    prep_whhx2<<<(GDIM * KW + 255) / 256, 256>>>(W_hh);
    prep_wout<<<(VOC * EMBD / 4 + 255) / 256, 256>>>(W_out);

    // 2) xpre = emb @ W_ih^T + b_ih + b_hh  (3xTF32 via extended K, no cvt)
    gemm_pre<128, 128, 2, 4, 256, false><<<dim3(GDIM / 128, MPAD / 128, 1), 256>>>(
        p_embext, p_wihext, p_xpre, b_ih, b_hh, MPAD, GDIM, KEXT, KEXT, KEXT);

    // 3) 19 fused recurrent steps (split-bf16, alu-free mainloop)
    for (int s = 0; s < NSTEP; s++)
        step_kernel<<<NCTA, 256>>>(s);

    // 4) logits = seq @ W_out^T + b_out  (pre-rounded tf32; M tiles on x so the
    //    10 CTAs sharing each W_out tile are co-resident -> W_out stays in L2)
    gemm_pre<128, 256, 4, 4, 512, true><<<dim3(MPAD / 128, VOC / 256, 1), 512>>>(
        p_seq, p_wout, out, b_out, nullptr, BB * TT, VOC, EMBD, EMBD, EMBD);
}